// round 9
// baseline (speedup 1.0000x reference)
#include <cuda_runtime.h>
#include <cstdint>

// ---------------- Problem constants ----------------
#define M_ENS 8
#define BATCH 4096
#define OBS_D 64
#define IN_D  96
#define H_D   1024
#define HEAD_N 192    // packed head cols (130 real, padded)

#define OFF_LV_O  (M_ENS * BATCH * OBS_D)
#define OFF_MU_R  (2 * M_ENS * BATCH * OBS_D)
#define OFF_LV_R  (OFF_MU_R + M_ENS * BATCH)

// ---------------- Scratch (static device memory) ----------------
__device__ __align__(256) float g_x[BATCH * IN_D];
__device__ __align__(256) float g_h0[(size_t)M_ENS * BATCH * H_D];
__device__ __align__(256) float g_h1[(size_t)M_ENS * BATCH * H_D];
__device__ __align__(256) float g_wt0[(size_t)M_ENS * H_D * IN_D];   // [m][n][k-perm]
__device__ __align__(256) float g_wt1[(size_t)M_ENS * H_D * H_D];
__device__ __align__(256) float g_wt2[(size_t)M_ENS * H_D * H_D];
__device__ __align__(256) float g_wth[(size_t)M_ENS * HEAD_N * H_D]; // [m][n][k-perm]
__device__ __align__(256) float g_bh[M_ENS * HEAD_N];

// ---------------- helpers ----------------
// in-group-of-8 k permutation: logical pair (t, t+4) lands adjacent -> LDS.64
__host__ __device__ __forceinline__ int kperm(int k) {
    return (k & ~7) | (((k & 3) << 1) | ((k >> 2) & 1));
}
__device__ __forceinline__ float tf32r(float x) {
    uint32_t u;
    asm("cvt.rna.tf32.f32 %0, %1;" : "=r"(u) : "f"(x));
    return __uint_as_float(u);
}
#define CPA(dst, src)  asm volatile("cp.async.cg.shared.global [%0], [%1], 16;" :: "r"(dst), "l"(src))
#define CPA_COMMIT()   asm volatile("cp.async.commit_group;" ::: "memory")
template <int N>
__device__ __forceinline__ void cpa_wait() {
    asm volatile("cp.async.wait_group %0;" :: "n"(N) : "memory");
}
__device__ __forceinline__ uint32_t smem_u32(const void* p) {
    uint32_t a;
    asm("{ .reg .u64 t; cvta.to.shared.u64 t, %1; cvt.u32.u64 %0, t; }" : "=r"(a) : "l"(p));
    return a;
}

__device__ __forceinline__ void mma_tf32(float* c, const uint32_t* a, const uint32_t* b) {
    asm volatile(
        "mma.sync.aligned.m16n8k8.row.col.f32.tf32.tf32.f32 "
        "{%0,%1,%2,%3}, {%4,%5,%6,%7}, {%8,%9}, {%0,%1,%2,%3};"
        : "+f"(c[0]), "+f"(c[1]), "+f"(c[2]), "+f"(c[3])
        : "r"(a[0]), "r"(a[1]), "r"(a[2]), "r"(a[3]), "r"(b[0]), "r"(b[1]));
}

__device__ __forceinline__ float softplusf(float x) {
    return fmaxf(x, 0.f) + log1pf(expf(-fabsf(x)));
}
__device__ __forceinline__ float clampv(float v) {
    v = 0.5f  - softplusf(0.5f - v);
    v = -10.f + softplusf(v + 10.f);
    return v;
}

// ---------------- Prep kernels (3 launches total) ----------------
__global__ void prep_fused(const float* __restrict__ obs, const float* __restrict__ act,
                           float* __restrict__ x,
                           const float* __restrict__ Wmu_o, const float* __restrict__ Wmu_r,
                           const float* __restrict__ Wv_o,  const float* __restrict__ Wv_r,
                           const float* __restrict__ bmu_o, const float* __restrict__ bmu_r,
                           const float* __restrict__ bv_o,  const float* __restrict__ bv_r,
                           float* __restrict__ wth, float* __restrict__ bh) {
    int idx = blockIdx.x * blockDim.x + threadIdx.x;
    if (idx < BATCH * IN_D) {
        int b = idx / IN_D, i = idx - b * IN_D;
        float v = (i < OBS_D) ? obs[b * OBS_D + i] : act[b * 32 + (i - OBS_D)];
        x[b * IN_D + kperm(i)] = tf32r(v);
    }
    if (idx < M_ENS * HEAD_N * H_D) {
        int m = idx / (HEAD_N * H_D);
        int rem = idx - m * (HEAD_N * H_D);
        int n = rem / H_D;
        int k = rem - n * H_D;
        size_t mk = (size_t)m * H_D + k;
        float v = 0.f;
        if (n < 64)        v = Wmu_o[mk * 64 + n];
        else if (n == 64)  v = Wmu_r[mk];
        else if (n < 129)  v = Wv_o[mk * 64 + (n - 65)];
        else if (n == 129) v = Wv_r[mk];
        wth[(size_t)m * (HEAD_N * H_D) + n * H_D + kperm(k)] = tf32r(v);
    }
    if (idx < M_ENS * HEAD_N) {
        int m = idx / HEAD_N, n = idx - m * HEAD_N;
        float v = 0.f;
        if (n < 64)        v = bmu_o[m * 64 + n];
        else if (n == 64)  v = bmu_r[m];
        else if (n < 129)  v = bv_o[m * 64 + n - 65];
        else if (n == 129) v = bv_r[m];
        bh[idx] = v;
    }
}

// src [m][K][N] -> dst [m][N][K-perm], rounded to tf32. DUAL selects pair by z>=8.
template <bool DUAL>
__global__ void transpose_round(const float* __restrict__ srcA, float* __restrict__ dstA,
                                const float* __restrict__ srcB, float* __restrict__ dstB,
                                int K, int N) {
    __shared__ float t[32][33];
    int z = blockIdx.z;
    int m = z & 7;
    const float* src = (DUAL && z >= 8) ? srcB : srcA;
    float* dst = (DUAL && z >= 8) ? dstB : dstA;
    int k0 = blockIdx.x * 32, n0 = blockIdx.y * 32;
    const float* s = src + (size_t)m * K * N;
    float* d = dst + (size_t)m * K * N;
    int tx = threadIdx.x, ty = threadIdx.y;
#pragma unroll
    for (int dy = 0; dy < 32; dy += 8)
        t[ty + dy][tx] = s[(size_t)(k0 + ty + dy) * N + n0 + tx];
    __syncthreads();
    int pk = k0 + kperm(tx);
#pragma unroll
    for (int dy = 0; dy < 32; dy += 8)
        d[(size_t)(n0 + ty + dy) * K + pk] = tf32r(t[tx][ty + dy]);
}

// ---------------- tf32 mma.sync GEMM ----------------
// C[m] (128 x 64) = A[m][row][k] @ Wt[m][col][k]^T (+bias, +act)
// 128 threads / 4 warps as 2x2 grid of 64x32 warp tiles.
// __launch_bounds__(128, 3): reg cap 168 -> ~50 regs of scheduling slack,
// 3 CTAs/SM (12 warps). 3-stage cp.async, BK=32.
// Rows = 32 words (128B) with float2-slot XOR swizzle:
//   word = r*32 + (cs ^ ((r&3)<<3))  -> conflict-free LDS.64 fragment loads.
template <int KTOT, bool HEADS>
__global__ __launch_bounds__(128, 3)
void gemm_mma(const float* __restrict__ A, size_t sAm, int ldA,
              const float* __restrict__ Wt, size_t sWm,
              const float* __restrict__ bias, int sBm,
              float* __restrict__ out, size_t sOm, int ldO) {
    constexpr int NKB = KTOT / 32;
    constexpr int BN = 64;
    constexpr int WN = 32;
    constexpr int MT = 4;               // WM = 64
    constexpr int NT = 4;               // WN/8
    constexpr int STAGE_F = (128 + BN) * 32;
    constexpr int A_NB4 = 128 * 8 / 128;   // 8 float4/thread for A tile
    constexpr int B_NB4 = BN * 8 / 128;    // 4 for B

    extern __shared__ float smem[];
    const uint32_t sb = smem_u32(smem);
    const int tid = threadIdx.x;
    const int wid = tid >> 5, lane = tid & 31;
    const int wm = wid & 1, wn = wid >> 1;
    const int gq = lane >> 2, tq = lane & 3;
    const int sw = (gq & 3) << 3;          // fragment swizzle (r&3 == gq&3 always)
    const int m = blockIdx.z;
    const int bm0 = blockIdx.x * 128;
    const int bn0 = blockIdx.y * BN;

    const float* Am  = A + sAm * m;
    const float* Wm  = Wt + sWm * m;
    const float* bm_ = bias + (size_t)sBm * m;

    auto fill = [&](int s, int kb) {
        uint32_t abase = sb + s * STAGE_F * 4;
#pragma unroll
        for (int p = 0; p < A_NB4; p++) {
            int f = tid + p * 128;
            int r = f >> 3, cv = f & 7;
            CPA(abase + r * 128 + ((cv * 16) ^ ((r & 3) << 5)),
                Am + (size_t)(bm0 + r) * ldA + kb * 32 + cv * 4);
        }
        uint32_t bbase = abase + 128 * 128;
#pragma unroll
        for (int p = 0; p < B_NB4; p++) {
            int f = tid + p * 128;
            int r = f >> 3, cv = f & 7;
            CPA(bbase + r * 128 + ((cv * 16) ^ ((r & 3) << 5)),
                Wm + (size_t)(bn0 + r) * KTOT + kb * 32 + cv * 4);
        }
        CPA_COMMIT();
    };

    float acc[MT][NT][4];
#pragma unroll
    for (int i = 0; i < MT; i++)
#pragma unroll
        for (int j = 0; j < NT; j++)
#pragma unroll
            for (int q = 0; q < 4; q++) acc[i][j][q] = 0.f;

    fill(0, 0);
    fill(1, 1);

    for (int kb = 0; kb < NKB; kb++) {
        if (kb == NKB - 1) cpa_wait<0>(); else cpa_wait<1>();
        __syncthreads();
        if (kb + 2 < NKB) fill((kb + 2) % 3, kb + 2);

        const float* As = smem + (kb % 3) * STAGE_F;
        const float* Bs = As + 128 * 32;
#pragma unroll
        for (int kk = 0; kk < 4; kk++) {
            int cs = (kk * 8 + tq * 2) ^ sw;   // swizzled slot of (k=tq, k=tq+4)
            uint32_t afr[MT][4], bfr[NT][2];
#pragma unroll
            for (int mt = 0; mt < MT; mt++) {
                int r = wm * 64 + mt * 16 + gq;
                float2 lo = *(const float2*)(As + r * 32 + cs);
                float2 hi = *(const float2*)(As + (r + 8) * 32 + cs);
                afr[mt][0] = __float_as_uint(lo.x);
                afr[mt][2] = __float_as_uint(lo.y);
                afr[mt][1] = __float_as_uint(hi.x);
                afr[mt][3] = __float_as_uint(hi.y);
            }
#pragma unroll
            for (int nt = 0; nt < NT; nt++) {
                int rn = wn * WN + nt * 8 + gq;
                float2 v = *(const float2*)(Bs + rn * 32 + cs);
                bfr[nt][0] = __float_as_uint(v.x);
                bfr[nt][1] = __float_as_uint(v.y);
            }
#pragma unroll
            for (int mt = 0; mt < MT; mt++)
#pragma unroll
                for (int nt = 0; nt < NT; nt++)
                    mma_tf32(acc[mt][nt], afr[mt], bfr[nt]);
        }
    }

    // ---- epilogue (register -> gmem) ----
    // acc q: c0 (row gq, col 2tq) c1 (+1 col) c2 (+8 row) c3 (+8 row, +1 col)
    if (!HEADS) {
        float* om = out + sOm * m;
#pragma unroll
        for (int nt = 0; nt < NT; nt++) {
            int gc0 = bn0 + wn * WN + nt * 8 + tq * 2;
            int pc0 = kperm(gc0), pc1 = kperm(gc0 + 1);
            float bA = bm_[gc0], bB = bm_[gc0 + 1];
#pragma unroll
            for (int mt = 0; mt < MT; mt++) {
                size_t gr = bm0 + wm * 64 + mt * 16 + gq;
                om[gr * ldO + pc0]       = tf32r(tanhf(acc[mt][nt][0] + bA));
                om[gr * ldO + pc1]       = tf32r(tanhf(acc[mt][nt][1] + bB));
                om[(gr + 8) * ldO + pc0] = tf32r(tanhf(acc[mt][nt][2] + bA));
                om[(gr + 8) * ldO + pc1] = tf32r(tanhf(acc[mt][nt][3] + bB));
            }
        }
    } else {
#pragma unroll
        for (int nt = 0; nt < NT; nt++) {
#pragma unroll
            for (int q2 = 0; q2 < 2; q2++) {
                int gc = bn0 + wn * WN + nt * 8 + tq * 2 + q2;
                if (gc >= 130) continue;
                float bb = bm_[gc];
#pragma unroll
                for (int mt = 0; mt < MT; mt++) {
#pragma unroll
                    for (int h = 0; h < 2; h++) {
                        int gr = bm0 + wm * 64 + mt * 16 + gq + h * 8;
                        float v = acc[mt][nt][h * 2 + q2] + bb;
                        if (gc < 64)
                            out[((size_t)m * BATCH + gr) * 64 + gc] = v;
                        else if (gc == 64)
                            out[OFF_MU_R + (size_t)m * BATCH + gr] = v;
                        else if (gc < 129)
                            out[OFF_LV_O + ((size_t)m * BATCH + gr) * 64 + (gc - 65)] = clampv(v);
                        else
                            out[OFF_LV_R + (size_t)m * BATCH + gr] = clampv(v);
                    }
                }
            }
        }
    }
}

// ---------------- Launch ----------------
extern "C" void kernel_launch(void* const* d_in, const int* in_sizes, int n_in,
                              void* d_out, int out_size) {
    const float* obs   = (const float*)d_in[0];
    const float* act   = (const float*)d_in[1];
    const float* W0    = (const float*)d_in[2];
    const float* b0    = (const float*)d_in[3];
    const float* W1    = (const float*)d_in[4];
    const float* b1    = (const float*)d_in[5];
    const float* W2    = (const float*)d_in[6];
    const float* b2    = (const float*)d_in[7];
    const float* Wmu_o = (const float*)d_in[8];
    const float* bmu_o = (const float*)d_in[9];
    const float* Wmu_r = (const float*)d_in[10];
    const float* bmu_r = (const float*)d_in[11];
    const float* Wv_o  = (const float*)d_in[12];
    const float* bv_o  = (const float*)d_in[13];
    const float* Wv_r  = (const float*)d_in[14];
    const float* bv_r  = (const float*)d_in[15];
    float* out = (float*)d_out;

    float *px, *ph0, *ph1, *pwt0, *pwt1, *pwt2, *pwth, *pbh;
    cudaGetSymbolAddress((void**)&px,   g_x);
    cudaGetSymbolAddress((void**)&ph0,  g_h0);
    cudaGetSymbolAddress((void**)&ph1,  g_h1);
    cudaGetSymbolAddress((void**)&pwt0, g_wt0);
    cudaGetSymbolAddress((void**)&pwt1, g_wt1);
    cudaGetSymbolAddress((void**)&pwt2, g_wt2);
    cudaGetSymbolAddress((void**)&pwth, g_wth);
    cudaGetSymbolAddress((void**)&pbh,  g_bh);

    // All GEMMs: BM=128, BN=64, 4 warps of 64x32, 3 CTAs/SM.
    const int SM_G = 3 * (128 + 64) * 32 * 4;    // 73728 B
    cudaFuncSetAttribute((const void*)gemm_mma<IN_D, false>,
                         cudaFuncAttributeMaxDynamicSharedMemorySize, SM_G);
    cudaFuncSetAttribute((const void*)gemm_mma<H_D, false>,
                         cudaFuncAttributeMaxDynamicSharedMemorySize, SM_G);
    cudaFuncSetAttribute((const void*)gemm_mma<H_D, true>,
                         cudaFuncAttributeMaxDynamicSharedMemorySize, SM_G);

    // prep: 3 launches (fused concat+pack; W0; W1+W2 merged)
    prep_fused<<<(M_ENS * HEAD_N * H_D + 255) / 256, 256>>>(
        obs, act, px, Wmu_o, Wmu_r, Wv_o, Wv_r, bmu_o, bmu_r, bv_o, bv_r, pwth, pbh);
    transpose_round<false><<<dim3(IN_D / 32, H_D / 32, M_ENS), dim3(32, 8)>>>(
        W0, pwt0, nullptr, nullptr, IN_D, H_D);
    transpose_round<true><<<dim3(H_D / 32, H_D / 32, 2 * M_ENS), dim3(32, 8)>>>(
        W1, pwt1, W2, pwt2, H_D, H_D);

    const size_t sH = (size_t)BATCH * H_D;
    dim3 gridL(BATCH / 128, H_D / 64, M_ENS);       // (32,16,8) = 4096 CTAs

    gemm_mma<IN_D, false><<<gridL, 128, SM_G>>>(
        px, 0, IN_D, pwt0, (size_t)H_D * IN_D, b0, H_D, ph0, sH, H_D);
    gemm_mma<H_D, false><<<gridL, 128, SM_G>>>(
        ph0, sH, H_D, pwt1, (size_t)H_D * H_D, b1, H_D, ph1, sH, H_D);
    gemm_mma<H_D, false><<<gridL, 128, SM_G>>>(
        ph1, sH, H_D, pwt2, (size_t)H_D * H_D, b2, H_D, ph0, sH, H_D);

    dim3 gridH(BATCH / 128, HEAD_N / 64, M_ENS);    // (32,3,8)
    gemm_mma<H_D, true><<<gridH, 128, SM_G>>>(
        ph0, sH, H_D, pwth, (size_t)HEAD_N * H_D, pbh, HEAD_N, out, 0, 0);
}

// round 10
// speedup vs baseline: 1.7931x; 1.7931x over previous
#include <cuda_runtime.h>
#include <cuda_fp16.h>
#include <cstdint>

// ---------------- Problem constants ----------------
#define M_ENS 8
#define BATCH 4096
#define OBS_D 64
#define IN_D  96
#define IN_PAD 128    // K padded to BK multiple
#define H_D   1024
#define HEAD_N 192    // packed head cols (130 real, padded)

#define OFF_LV_O  (M_ENS * BATCH * OBS_D)
#define OFF_MU_R  (2 * M_ENS * BATCH * OBS_D)
#define OFF_LV_R  (OFF_MU_R + M_ENS * BATCH)

// ---------------- Scratch (static device memory, fp16) ----------------
__device__ __align__(256) __half g_x[BATCH * IN_PAD];
__device__ __align__(256) __half g_h0[(size_t)M_ENS * BATCH * H_D];
__device__ __align__(256) __half g_h1[(size_t)M_ENS * BATCH * H_D];
__device__ __align__(256) __half g_wt0[(size_t)M_ENS * H_D * IN_PAD];  // [m][n][k]
__device__ __align__(256) __half g_wt1[(size_t)M_ENS * H_D * H_D];
__device__ __align__(256) __half g_wt2[(size_t)M_ENS * H_D * H_D];
__device__ __align__(256) __half g_wth[(size_t)M_ENS * HEAD_N * H_D];
__device__ __align__(256) float  g_bh[M_ENS * HEAD_N];

// ---------------- helpers ----------------
#define CPA(dst, src)  asm volatile("cp.async.cg.shared.global [%0], [%1], 16;" :: "r"(dst), "l"(src))
#define CPA_COMMIT()   asm volatile("cp.async.commit_group;" ::: "memory")
template <int N>
__device__ __forceinline__ void cpa_wait() {
    asm volatile("cp.async.wait_group %0;" :: "n"(N) : "memory");
}
__device__ __forceinline__ uint32_t smem_u32(const void* p) {
    uint32_t a;
    asm("{ .reg .u64 t; cvta.to.shared.u64 t, %1; cvt.u32.u64 %0, t; }" : "=r"(a) : "l"(p));
    return a;
}
__device__ __forceinline__ void ldm_x4(uint32_t* r, uint32_t addr) {
    asm volatile("ldmatrix.sync.aligned.m8n8.x4.shared.b16 {%0,%1,%2,%3}, [%4];"
        : "=r"(r[0]), "=r"(r[1]), "=r"(r[2]), "=r"(r[3]) : "r"(addr));
}
__device__ __forceinline__ void mma_f16(float* c, const uint32_t* a, const uint32_t* b) {
    asm volatile(
        "mma.sync.aligned.m16n8k16.row.col.f32.f16.f16.f32 "
        "{%0,%1,%2,%3}, {%4,%5,%6,%7}, {%8,%9}, {%0,%1,%2,%3};"
        : "+f"(c[0]), "+f"(c[1]), "+f"(c[2]), "+f"(c[3])
        : "r"(a[0]), "r"(a[1]), "r"(a[2]), "r"(a[3]), "r"(b[0]), "r"(b[1]));
}
__device__ __forceinline__ float softplusf(float x) {
    return fmaxf(x, 0.f) + log1pf(expf(-fabsf(x)));
}
__device__ __forceinline__ float clampv(float v) {
    v = 0.5f  - softplusf(0.5f - v);
    v = -10.f + softplusf(v + 10.f);
    return v;
}

// ---------------- Prep kernels (3 launches total) ----------------
__global__ void prep_fused(const float* __restrict__ obs, const float* __restrict__ act,
                           __half* __restrict__ x, __half* __restrict__ wt0,
                           const float* __restrict__ Wmu_o, const float* __restrict__ Wmu_r,
                           const float* __restrict__ Wv_o,  const float* __restrict__ Wv_r,
                           const float* __restrict__ bmu_o, const float* __restrict__ bmu_r,
                           const float* __restrict__ bv_o,  const float* __restrict__ bv_r,
                           __half* __restrict__ wth, float* __restrict__ bh) {
    int idx = blockIdx.x * blockDim.x + threadIdx.x;
    if (idx < BATCH * IN_PAD) {        // x concat + pad
        int b = idx / IN_PAD, i = idx - b * IN_PAD;
        float v = 0.f;
        if (i < OBS_D) v = obs[b * OBS_D + i];
        else if (i < IN_D) v = act[b * 32 + (i - OBS_D)];
        x[idx] = __float2half(v);
    }
    if (idx < M_ENS * HEAD_N * H_D) {  // head weight pack (transposed [n][k])
        int m = idx / (HEAD_N * H_D);
        int rem = idx - m * (HEAD_N * H_D);
        int n = rem / H_D;
        int k = rem - n * H_D;
        size_t mk = (size_t)m * H_D + k;
        float v = 0.f;
        if (n < 64)        v = Wmu_o[mk * 64 + n];
        else if (n == 64)  v = Wmu_r[mk];
        else if (n < 129)  v = Wv_o[mk * 64 + (n - 65)];
        else if (n == 129) v = Wv_r[mk];
        wth[idx] = __float2half(v);
    }
    if (idx < M_ENS * H_D * 32) {      // wt0 k-pad [96,128) zero
        int m = idx / (H_D * 32);
        int rem = idx - m * (H_D * 32);
        int n = rem >> 5, kk = rem & 31;
        wt0[(size_t)m * H_D * IN_PAD + n * IN_PAD + IN_D + kk] = __float2half(0.f);
    }
    if (idx < M_ENS * HEAD_N) {        // head bias pack
        int m = idx / HEAD_N, n = idx - m * HEAD_N;
        float v = 0.f;
        if (n < 64)        v = bmu_o[m * 64 + n];
        else if (n == 64)  v = bmu_r[m];
        else if (n < 129)  v = bv_o[m * 64 + n - 65];
        else if (n == 129) v = bv_r[m];
        bh[idx] = v;
    }
}

// src [m][K][N] f32 -> dst [m][N][ldDst] fp16. DUAL selects pair by z>=8.
template <bool DUAL>
__global__ void transpose_h(const float* __restrict__ srcA, __half* __restrict__ dstA,
                            const float* __restrict__ srcB, __half* __restrict__ dstB,
                            int K, int N, int ldDst) {
    __shared__ float t[32][33];
    int z = blockIdx.z;
    int m = z & 7;
    const float* src = (DUAL && z >= 8) ? srcB : srcA;
    __half* dst = (DUAL && z >= 8) ? dstB : dstA;
    int k0 = blockIdx.x * 32, n0 = blockIdx.y * 32;
    const float* s = src + (size_t)m * K * N;
    __half* d = dst + (size_t)m * N * ldDst;
    int tx = threadIdx.x, ty = threadIdx.y;
#pragma unroll
    for (int dy = 0; dy < 32; dy += 8)
        t[ty + dy][tx] = s[(size_t)(k0 + ty + dy) * N + n0 + tx];
    __syncthreads();
#pragma unroll
    for (int dy = 0; dy < 32; dy += 8)
        d[(size_t)(n0 + ty + dy) * ldDst + k0 + tx] = __float2half(t[tx][ty + dy]);
}

// ---------------- fp16 mma.sync GEMM ----------------
// C[m] (128 x 64) = A[m][row][k] @ Wt[m][col][k]^T (+bias, +act).  f32 accum.
// 128 threads / 4 warps as 2x2 of 64x32 warp tiles. 3-stage cp.async, BK=64.
// Smem rows = 128B (64 halves), SW128 swizzle: unit' = unit ^ (row&7).
// Fragments via ldmatrix.x4 (conflict-free under SW128).
template <int KTOT, bool HEADS>
__global__ __launch_bounds__(128, 3)
void gemm_h(const __half* __restrict__ A, size_t sAm, int ldA,
            const __half* __restrict__ Wt, size_t sWm,
            const float* __restrict__ bias, int sBm,
            void* __restrict__ outv, size_t sOm, int ldO) {
    constexpr int NKB = KTOT / 64;
    constexpr int BN = 64;
    constexpr int MT = 4;               // 64-row warp tile
    constexpr int NT = 4;               // 32-col warp tile
    constexpr int STAGE_B = (128 + BN) * 128;   // bytes per stage (24KB)

    extern __shared__ char smem[];
    const uint32_t sb = smem_u32(smem);
    const int tid = threadIdx.x;
    const int wid = tid >> 5, lane = tid & 31;
    const int wm = wid & 1, wn = wid >> 1;
    const int gq = lane >> 2, tq = lane & 3;
    const int l15 = lane & 15, hi = lane >> 4, xr = lane & 7;
    const int m = blockIdx.z;
    const int bm0 = blockIdx.x * 128;
    const int bn0 = blockIdx.y * BN;

    const __half* Am  = A + sAm * m;
    const __half* Wm  = Wt + sWm * m;
    const float*  bm_ = bias + (size_t)sBm * m;

    auto fill = [&](int s, int kb) {
        uint32_t abase = sb + s * STAGE_B;
#pragma unroll
        for (int p = 0; p < 8; p++) {                 // A: 128 rows x 8 units
            int f = tid + p * 128;
            int r = f >> 3, u = f & 7;
            CPA(abase + r * 128 + ((u ^ (r & 7)) << 4),
                Am + (size_t)(bm0 + r) * ldA + kb * 64 + u * 8);
        }
        uint32_t bbase = abase + 128 * 128;
#pragma unroll
        for (int p = 0; p < 4; p++) {                 // B: 64 rows x 8 units
            int f = tid + p * 128;
            int r = f >> 3, u = f & 7;
            CPA(bbase + r * 128 + ((u ^ (r & 7)) << 4),
                Wm + (size_t)(bn0 + r) * KTOT + kb * 64 + u * 8);
        }
        CPA_COMMIT();
    };

    float acc[MT][NT][4];
#pragma unroll
    for (int i = 0; i < MT; i++)
#pragma unroll
        for (int j = 0; j < NT; j++)
#pragma unroll
            for (int q = 0; q < 4; q++) acc[i][j][q] = 0.f;

    // per-lane ldmatrix row bases
    const uint32_t aRow = (wm * 64 + l15) * 128;
    const uint32_t bRow = (wn * 32 + l15) * 128;

    fill(0, 0);
    fill(1, 1);

    for (int kb = 0; kb < NKB; kb++) {
        if (kb == NKB - 1) cpa_wait<0>(); else cpa_wait<1>();
        __syncthreads();
        if (kb + 2 < NKB) fill((kb + 2) % 3, kb + 2);

        const uint32_t aS = sb + (kb % 3) * STAGE_B;
        const uint32_t bS = aS + 128 * 128;
#pragma unroll
        for (int kk = 0; kk < 4; kk++) {              // 4 x k16
            const uint32_t koff = (uint32_t)(((kk * 2 + hi) ^ xr) << 4);
            uint32_t afr[MT][4], bfr[NT][2];
#pragma unroll
            for (int mt = 0; mt < MT; mt++)
                ldm_x4(afr[mt], aS + aRow + mt * 2048 + koff);
#pragma unroll
            for (int ntp = 0; ntp < 2; ntp++) {       // B x4 covers 2 n-tiles
                uint32_t r[4];
                ldm_x4(r, bS + bRow + ntp * 2048 + koff);
                bfr[ntp * 2][0]     = r[0];
                bfr[ntp * 2 + 1][0] = r[1];
                bfr[ntp * 2][1]     = r[2];
                bfr[ntp * 2 + 1][1] = r[3];
            }
#pragma unroll
            for (int mt = 0; mt < MT; mt++)
#pragma unroll
                for (int nt = 0; nt < NT; nt++)
                    mma_f16(acc[mt][nt], afr[mt], bfr[nt]);
        }
    }

    // ---- epilogue ----
    // acc q: c0 (row gq, col 2tq) c1 (+1 col) c2 (+8 row) c3 (+8 row, +1 col)
    if (!HEADS) {
        __half* om = (__half*)outv + sOm * m;
#pragma unroll
        for (int nt = 0; nt < NT; nt++) {
            int gc0 = bn0 + wn * 32 + nt * 8 + tq * 2;
            float bA = bm_[gc0], bB = bm_[gc0 + 1];
#pragma unroll
            for (int mt = 0; mt < MT; mt++) {
                size_t gr = bm0 + wm * 64 + mt * 16 + gq;
                __half2 v0 = __floats2half2_rn(tanhf(acc[mt][nt][0] + bA),
                                               tanhf(acc[mt][nt][1] + bB));
                __half2 v1 = __floats2half2_rn(tanhf(acc[mt][nt][2] + bA),
                                               tanhf(acc[mt][nt][3] + bB));
                *(__half2*)(om + gr * ldO + gc0)       = v0;
                *(__half2*)(om + (gr + 8) * ldO + gc0) = v1;
            }
        }
    } else {
        float* out = (float*)outv;
#pragma unroll
        for (int nt = 0; nt < NT; nt++) {
#pragma unroll
            for (int q2 = 0; q2 < 2; q2++) {
                int gc = bn0 + wn * 32 + nt * 8 + tq * 2 + q2;
                if (gc >= 130) continue;
                float bb = bm_[gc];
#pragma unroll
                for (int mt = 0; mt < MT; mt++) {
#pragma unroll
                    for (int h = 0; h < 2; h++) {
                        int gr = bm0 + wm * 64 + mt * 16 + gq + h * 8;
                        float v = acc[mt][nt][h * 2 + q2] + bb;
                        if (gc < 64)
                            out[((size_t)m * BATCH + gr) * 64 + gc] = v;
                        else if (gc == 64)
                            out[OFF_MU_R + (size_t)m * BATCH + gr] = v;
                        else if (gc < 129)
                            out[OFF_LV_O + ((size_t)m * BATCH + gr) * 64 + (gc - 65)] = clampv(v);
                        else
                            out[OFF_LV_R + (size_t)m * BATCH + gr] = clampv(v);
                    }
                }
            }
        }
    }
}

// ---------------- Launch ----------------
extern "C" void kernel_launch(void* const* d_in, const int* in_sizes, int n_in,
                              void* d_out, int out_size) {
    const float* obs   = (const float*)d_in[0];
    const float* act   = (const float*)d_in[1];
    const float* W0    = (const float*)d_in[2];
    const float* b0    = (const float*)d_in[3];
    const float* W1    = (const float*)d_in[4];
    const float* b1    = (const float*)d_in[5];
    const float* W2    = (const float*)d_in[6];
    const float* b2    = (const float*)d_in[7];
    const float* Wmu_o = (const float*)d_in[8];
    const float* bmu_o = (const float*)d_in[9];
    const float* Wmu_r = (const float*)d_in[10];
    const float* bmu_r = (const float*)d_in[11];
    const float* Wv_o  = (const float*)d_in[12];
    const float* bv_o  = (const float*)d_in[13];
    const float* Wv_r  = (const float*)d_in[14];
    const float* bv_r  = (const float*)d_in[15];

    __half *px, *ph0, *ph1, *pwt0, *pwt1, *pwt2, *pwth;
    float *pbh;
    cudaGetSymbolAddress((void**)&px,   g_x);
    cudaGetSymbolAddress((void**)&ph0,  g_h0);
    cudaGetSymbolAddress((void**)&ph1,  g_h1);
    cudaGetSymbolAddress((void**)&pwt0, g_wt0);
    cudaGetSymbolAddress((void**)&pwt1, g_wt1);
    cudaGetSymbolAddress((void**)&pwt2, g_wt2);
    cudaGetSymbolAddress((void**)&pwth, g_wth);
    cudaGetSymbolAddress((void**)&pbh,  g_bh);

    const int SM_G = 3 * (128 + 64) * 128;       // 73728 B
    cudaFuncSetAttribute((const void*)gemm_h<IN_PAD, false>,
                         cudaFuncAttributeMaxDynamicSharedMemorySize, SM_G);
    cudaFuncSetAttribute((const void*)gemm_h<H_D, false>,
                         cudaFuncAttributeMaxDynamicSharedMemorySize, SM_G);
    cudaFuncSetAttribute((const void*)gemm_h<H_D, true>,
                         cudaFuncAttributeMaxDynamicSharedMemorySize, SM_G);

    // prep: 3 launches
    prep_fused<<<(M_ENS * HEAD_N * H_D + 255) / 256, 256>>>(
        obs, act, px, pwt0, Wmu_o, Wmu_r, Wv_o, Wv_r,
        bmu_o, bmu_r, bv_o, bv_r, pwth, pbh);
    transpose_h<false><<<dim3(IN_D / 32, H_D / 32, M_ENS), dim3(32, 8)>>>(
        W0, pwt0, nullptr, nullptr, IN_D, H_D, IN_PAD);
    transpose_h<true><<<dim3(H_D / 32, H_D / 32, 2 * M_ENS), dim3(32, 8)>>>(
        W1, pwt1, W2, pwt2, H_D, H_D, H_D);

    const size_t sH = (size_t)BATCH * H_D;
    dim3 gridL(BATCH / 128, H_D / 64, M_ENS);       // (32,16,8)

    gemm_h<IN_PAD, false><<<gridL, 128, SM_G>>>(
        px, 0, IN_PAD, pwt0, (size_t)H_D * IN_PAD, b0, H_D, ph0, sH, H_D);
    gemm_h<H_D, false><<<gridL, 128, SM_G>>>(
        ph0, sH, H_D, pwt1, (size_t)H_D * H_D, b1, H_D, ph1, sH, H_D);
    gemm_h<H_D, false><<<gridL, 128, SM_G>>>(
        ph1, sH, H_D, pwt2, (size_t)H_D * H_D, b2, H_D, ph0, sH, H_D);

    dim3 gridH(BATCH / 128, HEAD_N / 64, M_ENS);    // (32,3,8)
    gemm_h<H_D, true><<<gridH, 128, SM_G>>>(
        ph0, sH, H_D, pwth, (size_t)HEAD_N * H_D, pbh, HEAD_N, d_out, 0, 0);
}

// round 11
// speedup vs baseline: 1.8505x; 1.0320x over previous
#include <cuda_runtime.h>
#include <cuda_fp16.h>
#include <cstdint>

// ---------------- Problem constants ----------------
#define M_ENS 8
#define BATCH 4096
#define OBS_D 64
#define IN_D  96
#define IN_PAD 128    // K padded to BK multiple
#define H_D   1024
#define HEAD_N 192    // packed head cols (130 real, padded)

#define OFF_LV_O  (M_ENS * BATCH * OBS_D)
#define OFF_MU_R  (2 * M_ENS * BATCH * OBS_D)
#define OFF_LV_R  (OFF_MU_R + M_ENS * BATCH)

// ---------------- Scratch (static device memory, fp16) ----------------
__device__ __align__(256) __half g_x[BATCH * IN_PAD];
__device__ __align__(256) __half g_h0[(size_t)M_ENS * BATCH * H_D];
__device__ __align__(256) __half g_h1[(size_t)M_ENS * BATCH * H_D];
__device__ __align__(256) __half g_wt0[(size_t)M_ENS * H_D * IN_PAD];  // [m][n][k]
__device__ __align__(256) __half g_wt1[(size_t)M_ENS * H_D * H_D];
__device__ __align__(256) __half g_wt2[(size_t)M_ENS * H_D * H_D];
__device__ __align__(256) __half g_wth[(size_t)M_ENS * HEAD_N * H_D];
__device__ __align__(256) float  g_bh[M_ENS * HEAD_N];

// ---------------- helpers ----------------
#define CPA(dst, src)  asm volatile("cp.async.cg.shared.global [%0], [%1], 16;" :: "r"(dst), "l"(src))
#define CPA_COMMIT()   asm volatile("cp.async.commit_group;" ::: "memory")
template <int N>
__device__ __forceinline__ void cpa_wait() {
    asm volatile("cp.async.wait_group %0;" :: "n"(N) : "memory");
}
__device__ __forceinline__ uint32_t smem_u32(const void* p) {
    uint32_t a;
    asm("{ .reg .u64 t; cvta.to.shared.u64 t, %1; cvt.u32.u64 %0, t; }" : "=r"(a) : "l"(p));
    return a;
}
__device__ __forceinline__ void ldm_x4(uint32_t* r, uint32_t addr) {
    asm volatile("ldmatrix.sync.aligned.m8n8.x4.shared.b16 {%0,%1,%2,%3}, [%4];"
        : "=r"(r[0]), "=r"(r[1]), "=r"(r[2]), "=r"(r[3]) : "r"(addr));
}
__device__ __forceinline__ void mma_f16(float* c, const uint32_t* a, const uint32_t* b) {
    asm volatile(
        "mma.sync.aligned.m16n8k16.row.col.f32.f16.f16.f32 "
        "{%0,%1,%2,%3}, {%4,%5,%6,%7}, {%8,%9}, {%0,%1,%2,%3};"
        : "+f"(c[0]), "+f"(c[1]), "+f"(c[2]), "+f"(c[3])
        : "r"(a[0]), "r"(a[1]), "r"(a[2]), "r"(a[3]), "r"(b[0]), "r"(b[1]));
}
__device__ __forceinline__ float softplusf(float x) {
    return fmaxf(x, 0.f) + log1pf(expf(-fabsf(x)));
}
__device__ __forceinline__ float clampv(float v) {
    v = 0.5f  - softplusf(0.5f - v);
    v = -10.f + softplusf(v + 10.f);
    return v;
}

// ---------------- Prep kernels (3 launches total) ----------------
__global__ void prep_fused(const float* __restrict__ obs, const float* __restrict__ act,
                           __half* __restrict__ x, __half* __restrict__ wt0,
                           const float* __restrict__ Wmu_o, const float* __restrict__ Wmu_r,
                           const float* __restrict__ Wv_o,  const float* __restrict__ Wv_r,
                           const float* __restrict__ bmu_o, const float* __restrict__ bmu_r,
                           const float* __restrict__ bv_o,  const float* __restrict__ bv_r,
                           __half* __restrict__ wth, float* __restrict__ bh) {
    int idx = blockIdx.x * blockDim.x + threadIdx.x;
    if (idx < BATCH * IN_PAD) {        // x concat + pad
        int b = idx / IN_PAD, i = idx - b * IN_PAD;
        float v = 0.f;
        if (i < OBS_D) v = obs[b * OBS_D + i];
        else if (i < IN_D) v = act[b * 32 + (i - OBS_D)];
        x[idx] = __float2half(v);
    }
    if (idx < M_ENS * HEAD_N * H_D) {  // head weight pack (transposed [n][k])
        int m = idx / (HEAD_N * H_D);
        int rem = idx - m * (HEAD_N * H_D);
        int n = rem / H_D;
        int k = rem - n * H_D;
        size_t mk = (size_t)m * H_D + k;
        float v = 0.f;
        if (n < 64)        v = Wmu_o[mk * 64 + n];
        else if (n == 64)  v = Wmu_r[mk];
        else if (n < 129)  v = Wv_o[mk * 64 + (n - 65)];
        else if (n == 129) v = Wv_r[mk];
        wth[idx] = __float2half(v);
    }
    if (idx < M_ENS * H_D * 32) {      // wt0 k-pad [96,128) zero
        int m = idx / (H_D * 32);
        int rem = idx - m * (H_D * 32);
        int n = rem >> 5, kk = rem & 31;
        wt0[(size_t)m * H_D * IN_PAD + n * IN_PAD + IN_D + kk] = __float2half(0.f);
    }
    if (idx < M_ENS * HEAD_N) {        // head bias pack
        int m = idx / HEAD_N, n = idx - m * HEAD_N;
        float v = 0.f;
        if (n < 64)        v = bmu_o[m * 64 + n];
        else if (n == 64)  v = bmu_r[m];
        else if (n < 129)  v = bv_o[m * 64 + n - 65];
        else if (n == 129) v = bv_r[m];
        bh[idx] = v;
    }
}

// src [m][K][N] f32 -> dst [m][N][ldDst] fp16. DUAL selects pair by z>=8.
template <bool DUAL>
__global__ void transpose_h(const float* __restrict__ srcA, __half* __restrict__ dstA,
                            const float* __restrict__ srcB, __half* __restrict__ dstB,
                            int K, int N, int ldDst) {
    __shared__ float t[32][33];
    int z = blockIdx.z;
    int m = z & 7;
    const float* src = (DUAL && z >= 8) ? srcB : srcA;
    __half* dst = (DUAL && z >= 8) ? dstB : dstA;
    int k0 = blockIdx.x * 32, n0 = blockIdx.y * 32;
    const float* s = src + (size_t)m * K * N;
    __half* d = dst + (size_t)m * N * ldDst;
    int tx = threadIdx.x, ty = threadIdx.y;
#pragma unroll
    for (int dy = 0; dy < 32; dy += 8)
        t[ty + dy][tx] = s[(size_t)(k0 + ty + dy) * N + n0 + tx];
    __syncthreads();
#pragma unroll
    for (int dy = 0; dy < 32; dy += 8)
        d[(size_t)(n0 + ty + dy) * ldDst + k0 + tx] = __float2half(t[tx][ty + dy]);
}

// ---------------- fp16 mma.sync GEMM ----------------
// C[m] (128 x BN) = A[m][row][k] @ Wt[m][col][k]^T (+bias, +act).  f32 accum.
// 2*BN threads: warps as 2 x (BN/32) grid of 64x32 warp tiles.
// 3-stage cp.async, BK=64. Smem rows = 128B, SW128 swizzle: unit' = unit ^ (row&7).
// Fragments via ldmatrix.x4 (conflict-free).
template <int KTOT, int BN, bool HEADS>
__global__ __launch_bounds__(2 * BN, BN == 128 ? 2 : 3)
void gemm_h(const __half* __restrict__ A, size_t sAm, int ldA,
            const __half* __restrict__ Wt, size_t sWm,
            const float* __restrict__ bias, int sBm,
            void* __restrict__ outv, size_t sOm, int ldO) {
    constexpr int NKB = KTOT / 64;
    constexpr int THREADS = 2 * BN;
    constexpr int MT = 4;               // 64-row warp tile
    constexpr int NT = 4;               // 32-col warp tile
    constexpr int STAGE_B = (128 + BN) * 128;   // bytes per stage
    constexpr int A_IT = 1024 / THREADS;
    constexpr int B_IT = BN * 8 / THREADS;      // = 4

    extern __shared__ char smem[];
    const uint32_t sb = smem_u32(smem);
    const int tid = threadIdx.x;
    const int wid = tid >> 5, lane = tid & 31;
    const int wm = wid & 1, wn = wid >> 1;
    const int gq = lane >> 2, tq = lane & 3;
    const int l15 = lane & 15, hi = lane >> 4, xr = lane & 7;
    const int m = blockIdx.z;
    const int bm0 = blockIdx.x * 128;
    const int bn0 = blockIdx.y * BN;

    const __half* Am  = A + sAm * m;
    const __half* Wm  = Wt + sWm * m;
    const float*  bm_ = bias + (size_t)sBm * m;

    auto fill = [&](int s, int kb) {
        uint32_t abase = sb + s * STAGE_B;
#pragma unroll
        for (int p = 0; p < A_IT; p++) {              // A: 128 rows x 8 units
            int f = tid + p * THREADS;
            int r = f >> 3, u = f & 7;
            CPA(abase + r * 128 + ((u ^ (r & 7)) << 4),
                Am + (size_t)(bm0 + r) * ldA + kb * 64 + u * 8);
        }
        uint32_t bbase = abase + 128 * 128;
#pragma unroll
        for (int p = 0; p < B_IT; p++) {              // B: BN rows x 8 units
            int f = tid + p * THREADS;
            int r = f >> 3, u = f & 7;
            CPA(bbase + r * 128 + ((u ^ (r & 7)) << 4),
                Wm + (size_t)(bn0 + r) * KTOT + kb * 64 + u * 8);
        }
        CPA_COMMIT();
    };

    float acc[MT][NT][4];
#pragma unroll
    for (int i = 0; i < MT; i++)
#pragma unroll
        for (int j = 0; j < NT; j++)
#pragma unroll
            for (int q = 0; q < 4; q++) acc[i][j][q] = 0.f;

    // per-lane ldmatrix row bases
    const uint32_t aRow = (wm * 64 + l15) * 128;
    const uint32_t bRow = (wn * 32 + l15) * 128;

    fill(0, 0);
    fill(1, 1);

    for (int kb = 0; kb < NKB; kb++) {
        if (kb == NKB - 1) cpa_wait<0>(); else cpa_wait<1>();
        __syncthreads();
        if (kb + 2 < NKB) fill((kb + 2) % 3, kb + 2);

        const uint32_t aS = sb + (kb % 3) * STAGE_B;
        const uint32_t bS = aS + 128 * 128;
#pragma unroll
        for (int kk = 0; kk < 4; kk++) {              // 4 x k16
            const uint32_t koff = (uint32_t)(((kk * 2 + hi) ^ xr) << 4);
            uint32_t afr[MT][4], bfr[NT][2];
#pragma unroll
            for (int mt = 0; mt < MT; mt++)
                ldm_x4(afr[mt], aS + aRow + mt * 2048 + koff);
#pragma unroll
            for (int ntp = 0; ntp < 2; ntp++) {       // B x4 covers 2 n-tiles
                uint32_t r[4];
                ldm_x4(r, bS + bRow + ntp * 2048 + koff);
                bfr[ntp * 2][0]     = r[0];
                bfr[ntp * 2 + 1][0] = r[1];
                bfr[ntp * 2][1]     = r[2];
                bfr[ntp * 2 + 1][1] = r[3];
            }
#pragma unroll
            for (int mt = 0; mt < MT; mt++)
#pragma unroll
                for (int nt = 0; nt < NT; nt++)
                    mma_f16(acc[mt][nt], afr[mt], bfr[nt]);
        }
    }

    // ---- epilogue ----
    // acc q: c0 (row gq, col 2tq) c1 (+1 col) c2 (+8 row) c3 (+8 row, +1 col)
    if (!HEADS) {
        __half* om = (__half*)outv + sOm * m;
#pragma unroll
        for (int nt = 0; nt < NT; nt++) {
            int gc0 = bn0 + wn * 32 + nt * 8 + tq * 2;
            float bA = bm_[gc0], bB = bm_[gc0 + 1];
#pragma unroll
            for (int mt = 0; mt < MT; mt++) {
                size_t gr = bm0 + wm * 64 + mt * 16 + gq;
                __half2 v0 = __floats2half2_rn(tanhf(acc[mt][nt][0] + bA),
                                               tanhf(acc[mt][nt][1] + bB));
                __half2 v1 = __floats2half2_rn(tanhf(acc[mt][nt][2] + bA),
                                               tanhf(acc[mt][nt][3] + bB));
                *(__half2*)(om + gr * ldO + gc0)       = v0;
                *(__half2*)(om + (gr + 8) * ldO + gc0) = v1;
            }
        }
    } else {
        float* out = (float*)outv;
#pragma unroll
        for (int nt = 0; nt < NT; nt++) {
#pragma unroll
            for (int q2 = 0; q2 < 2; q2++) {
                int gc = bn0 + wn * 32 + nt * 8 + tq * 2 + q2;
                if (gc >= 130) continue;
                float bb = bm_[gc];
#pragma unroll
                for (int mt = 0; mt < MT; mt++) {
#pragma unroll
                    for (int h = 0; h < 2; h++) {
                        int gr = bm0 + wm * 64 + mt * 16 + gq + h * 8;
                        float v = acc[mt][nt][h * 2 + q2] + bb;
                        if (gc < 64)
                            out[((size_t)m * BATCH + gr) * 64 + gc] = v;
                        else if (gc == 64)
                            out[OFF_MU_R + (size_t)m * BATCH + gr] = v;
                        else if (gc < 129)
                            out[OFF_LV_O + ((size_t)m * BATCH + gr) * 64 + (gc - 65)] = clampv(v);
                        else
                            out[OFF_LV_R + (size_t)m * BATCH + gr] = clampv(v);
                    }
                }
            }
        }
    }
}

// ---------------- Launch ----------------
extern "C" void kernel_launch(void* const* d_in, const int* in_sizes, int n_in,
                              void* d_out, int out_size) {
    const float* obs   = (const float*)d_in[0];
    const float* act   = (const float*)d_in[1];
    const float* W0    = (const float*)d_in[2];
    const float* b0    = (const float*)d_in[3];
    const float* W1    = (const float*)d_in[4];
    const float* b1    = (const float*)d_in[5];
    const float* W2    = (const float*)d_in[6];
    const float* b2    = (const float*)d_in[7];
    const float* Wmu_o = (const float*)d_in[8];
    const float* bmu_o = (const float*)d_in[9];
    const float* Wmu_r = (const float*)d_in[10];
    const float* bmu_r = (const float*)d_in[11];
    const float* Wv_o  = (const float*)d_in[12];
    const float* bv_o  = (const float*)d_in[13];
    const float* Wv_r  = (const float*)d_in[14];
    const float* bv_r  = (const float*)d_in[15];

    __half *px, *ph0, *ph1, *pwt0, *pwt1, *pwt2, *pwth;
    float *pbh;
    cudaGetSymbolAddress((void**)&px,   g_x);
    cudaGetSymbolAddress((void**)&ph0,  g_h0);
    cudaGetSymbolAddress((void**)&ph1,  g_h1);
    cudaGetSymbolAddress((void**)&pwt0, g_wt0);
    cudaGetSymbolAddress((void**)&pwt1, g_wt1);
    cudaGetSymbolAddress((void**)&pwt2, g_wt2);
    cudaGetSymbolAddress((void**)&pwth, g_wth);
    cudaGetSymbolAddress((void**)&pbh,  g_bh);

    // Layers: BM=128, BN=128, 8 warps of 64x32, 2 CTAs/SM (96KB smem).
    // Heads:  BM=128, BN=64, 4 warps, 3 CTAs/SM (72KB).
    const int SM_L = 3 * (128 + 128) * 128;      // 98304 B
    const int SM_H = 3 * (128 + 64) * 128;       // 73728 B
    cudaFuncSetAttribute((const void*)gemm_h<IN_PAD, 128, false>,
                         cudaFuncAttributeMaxDynamicSharedMemorySize, SM_L);
    cudaFuncSetAttribute((const void*)gemm_h<H_D, 128, false>,
                         cudaFuncAttributeMaxDynamicSharedMemorySize, SM_L);
    cudaFuncSetAttribute((const void*)gemm_h<H_D, 64, true>,
                         cudaFuncAttributeMaxDynamicSharedMemorySize, SM_H);

    // prep: 3 launches
    prep_fused<<<(M_ENS * HEAD_N * H_D + 255) / 256, 256>>>(
        obs, act, px, pwt0, Wmu_o, Wmu_r, Wv_o, Wv_r,
        bmu_o, bmu_r, bv_o, bv_r, pwth, pbh);
    transpose_h<false><<<dim3(IN_D / 32, H_D / 32, M_ENS), dim3(32, 8)>>>(
        W0, pwt0, nullptr, nullptr, IN_D, H_D, IN_PAD);
    transpose_h<true><<<dim3(H_D / 32, H_D / 32, 2 * M_ENS), dim3(32, 8)>>>(
        W1, pwt1, W2, pwt2, H_D, H_D, H_D);

    const size_t sH = (size_t)BATCH * H_D;
    dim3 gridL(BATCH / 128, H_D / 128, M_ENS);      // (32,8,8) = 2048 CTAs

    gemm_h<IN_PAD, 128, false><<<gridL, 256, SM_L>>>(
        px, 0, IN_PAD, pwt0, (size_t)H_D * IN_PAD, b0, H_D, ph0, sH, H_D);
    gemm_h<H_D, 128, false><<<gridL, 256, SM_L>>>(
        ph0, sH, H_D, pwt1, (size_t)H_D * H_D, b1, H_D, ph1, sH, H_D);
    gemm_h<H_D, 128, false><<<gridL, 256, SM_L>>>(
        ph1, sH, H_D, pwt2, (size_t)H_D * H_D, b2, H_D, ph0, sH, H_D);

    dim3 gridH(BATCH / 128, HEAD_N / 64, M_ENS);    // (32,3,8)
    gemm_h<H_D, 64, true><<<gridH, 128, SM_H>>>(
        ph0, sH, H_D, pwth, (size_t)HEAD_N * H_D, pbh, HEAD_N, d_out, 0, 0);
}

// round 12
// speedup vs baseline: 1.8978x; 1.0255x over previous
#include <cuda_runtime.h>
#include <cuda_fp16.h>
#include <cstdint>

// ---------------- Problem constants ----------------
#define M_ENS 8
#define BATCH 4096
#define OBS_D 64
#define IN_D  96
#define IN_PAD 128    // K padded to BK multiple
#define H_D   1024
#define HEAD_N 192    // packed head cols (130 real, padded)

#define OFF_LV_O  (M_ENS * BATCH * OBS_D)
#define OFF_MU_R  (2 * M_ENS * BATCH * OBS_D)
#define OFF_LV_R  (OFF_MU_R + M_ENS * BATCH)

// ---------------- Scratch (static device memory, fp16) ----------------
__device__ __align__(256) __half g_x[BATCH * IN_PAD];
__device__ __align__(256) __half g_h0[(size_t)M_ENS * BATCH * H_D];
__device__ __align__(256) __half g_h1[(size_t)M_ENS * BATCH * H_D];
__device__ __align__(256) __half g_wt0[(size_t)M_ENS * H_D * IN_PAD];  // [m][n][k]
__device__ __align__(256) __half g_wt1[(size_t)M_ENS * H_D * H_D];
__device__ __align__(256) __half g_wt2[(size_t)M_ENS * H_D * H_D];
__device__ __align__(256) __half g_wth[(size_t)M_ENS * HEAD_N * H_D];
__device__ __align__(256) float  g_bh[M_ENS * HEAD_N];

// ---------------- helpers ----------------
#define CPA(dst, src)  asm volatile("cp.async.cg.shared.global [%0], [%1], 16;" :: "r"(dst), "l"(src))
#define CPA_COMMIT()   asm volatile("cp.async.commit_group;" ::: "memory")
template <int N>
__device__ __forceinline__ void cpa_wait() {
    asm volatile("cp.async.wait_group %0;" :: "n"(N) : "memory");
}
__device__ __forceinline__ uint32_t smem_u32(const void* p) {
    uint32_t a;
    asm("{ .reg .u64 t; cvta.to.shared.u64 t, %1; cvt.u32.u64 %0, t; }" : "=r"(a) : "l"(p));
    return a;
}
__device__ __forceinline__ void ldm_x4(uint32_t* r, uint32_t addr) {
    asm volatile("ldmatrix.sync.aligned.m8n8.x4.shared.b16 {%0,%1,%2,%3}, [%4];"
        : "=r"(r[0]), "=r"(r[1]), "=r"(r[2]), "=r"(r[3]) : "r"(addr));
}
__device__ __forceinline__ void mma_f16(float* c, const uint32_t* a, const uint32_t* b) {
    asm volatile(
        "mma.sync.aligned.m16n8k16.row.col.f32.f16.f16.f32 "
        "{%0,%1,%2,%3}, {%4,%5,%6,%7}, {%8,%9}, {%0,%1,%2,%3};"
        : "+f"(c[0]), "+f"(c[1]), "+f"(c[2]), "+f"(c[3])
        : "r"(a[0]), "r"(a[1]), "r"(a[2]), "r"(a[3]), "r"(b[0]), "r"(b[1]));
}
// fast tanh: 2 MUFU + few FMA; rel err ~1e-6. Clamp +-9 (tanh(9)==1.0 in fp16).
__device__ __forceinline__ float tanh_fast(float x) {
    x = fminf(fmaxf(x, -9.f), 9.f);
    float t = __expf(2.f * x);
    return __fdividef(t - 1.f, t + 1.f);
}
__device__ __forceinline__ float softplus_fast(float x) {
    return fmaxf(x, 0.f) + __logf(1.f + __expf(-fabsf(x)));
}
__device__ __forceinline__ float clampv(float v) {
    v = 0.5f  - softplus_fast(0.5f - v);
    v = -10.f + softplus_fast(v + 10.f);
    return v;
}

// ---------------- Prep kernels (3 launches total) ----------------
__global__ void prep_fused(const float* __restrict__ obs, const float* __restrict__ act,
                           __half* __restrict__ x, __half* __restrict__ wt0,
                           const float* __restrict__ Wmu_o, const float* __restrict__ Wmu_r,
                           const float* __restrict__ Wv_o,  const float* __restrict__ Wv_r,
                           const float* __restrict__ bmu_o, const float* __restrict__ bmu_r,
                           const float* __restrict__ bv_o,  const float* __restrict__ bv_r,
                           __half* __restrict__ wth, float* __restrict__ bh) {
    int idx = blockIdx.x * blockDim.x + threadIdx.x;
    if (idx < BATCH * IN_PAD) {        // x concat + pad
        int b = idx / IN_PAD, i = idx - b * IN_PAD;
        float v = 0.f;
        if (i < OBS_D) v = obs[b * OBS_D + i];
        else if (i < IN_D) v = act[b * 32 + (i - OBS_D)];
        x[idx] = __float2half(v);
    }
    if (idx < M_ENS * HEAD_N * H_D) {  // head weight pack (transposed [n][k])
        int m = idx / (HEAD_N * H_D);
        int rem = idx - m * (HEAD_N * H_D);
        int n = rem / H_D;
        int k = rem - n * H_D;
        size_t mk = (size_t)m * H_D + k;
        float v = 0.f;
        if (n < 64)        v = Wmu_o[mk * 64 + n];
        else if (n == 64)  v = Wmu_r[mk];
        else if (n < 129)  v = Wv_o[mk * 64 + (n - 65)];
        else if (n == 129) v = Wv_r[mk];
        wth[idx] = __float2half(v);
    }
    if (idx < M_ENS * H_D * 32) {      // wt0 k-pad [96,128) zero
        int m = idx / (H_D * 32);
        int rem = idx - m * (H_D * 32);
        int n = rem >> 5, kk = rem & 31;
        wt0[(size_t)m * H_D * IN_PAD + n * IN_PAD + IN_D + kk] = __float2half(0.f);
    }
    if (idx < M_ENS * HEAD_N) {        // head bias pack
        int m = idx / HEAD_N, n = idx - m * HEAD_N;
        float v = 0.f;
        if (n < 64)        v = bmu_o[m * 64 + n];
        else if (n == 64)  v = bmu_r[m];
        else if (n < 129)  v = bv_o[m * 64 + n - 65];
        else if (n == 129) v = bv_r[m];
        bh[idx] = v;
    }
}

// src [m][K][N] f32 -> dst [m][N][ldDst] fp16. DUAL selects pair by z>=8.
template <bool DUAL>
__global__ void transpose_h(const float* __restrict__ srcA, __half* __restrict__ dstA,
                            const float* __restrict__ srcB, __half* __restrict__ dstB,
                            int K, int N, int ldDst) {
    __shared__ float t[32][33];
    int z = blockIdx.z;
    int m = z & 7;
    const float* src = (DUAL && z >= 8) ? srcB : srcA;
    __half* dst = (DUAL && z >= 8) ? dstB : dstA;
    int k0 = blockIdx.x * 32, n0 = blockIdx.y * 32;
    const float* s = src + (size_t)m * K * N;
    __half* d = dst + (size_t)m * N * ldDst;
    int tx = threadIdx.x, ty = threadIdx.y;
#pragma unroll
    for (int dy = 0; dy < 32; dy += 8)
        t[ty + dy][tx] = s[(size_t)(k0 + ty + dy) * N + n0 + tx];
    __syncthreads();
#pragma unroll
    for (int dy = 0; dy < 32; dy += 8)
        d[(size_t)(n0 + ty + dy) * ldDst + k0 + tx] = __float2half(t[tx][ty + dy]);
}

// ---------------- fp16 mma.sync GEMM ----------------
// C[m] (128 x BN) = A[m][row][k] @ Wt[m][col][k]^T (+bias, +act).  f32 accum.
// ld of A and Wt is KTOT (compile-time). 2*BN threads, warps as 2 x (BN/32)
// grid of 64x32 warp tiles. 3-stage cp.async (BK=64), SW128 swizzle rows.
// Fills use pointer-increment addressing (no per-kb IMAD.WIDE chains).
template <int KTOT, int BN, bool HEADS>
__global__ __launch_bounds__(2 * BN, BN == 128 ? 2 : 3)
void gemm_h(const __half* __restrict__ A, size_t sAm,
            const __half* __restrict__ Wt, size_t sWm,
            const float* __restrict__ bias, int sBm,
            void* __restrict__ outv, size_t sOm, int ldO) {
    constexpr int NKB = KTOT / 64;
    constexpr int THREADS = 2 * BN;
    constexpr int MT = 4;               // 64-row warp tile
    constexpr int NT = 4;               // 32-col warp tile
    constexpr int STAGE_B = (128 + BN) * 128;   // bytes per stage
    constexpr int A_IT = 1024 / THREADS;
    constexpr int B_IT = BN * 8 / THREADS;
    constexpr int ROWS_P = THREADS / 8;         // rows per p-step

    extern __shared__ char smem[];
    const uint32_t sb = smem_u32(smem);
    const int tid = threadIdx.x;
    const int wid = tid >> 5, lane = tid & 31;
    const int wm = wid & 1, wn = wid >> 1;
    const int gq = lane >> 2, tq = lane & 3;
    const int l15 = lane & 15, hi = lane >> 4, xr = lane & 7;
    const int m = blockIdx.z;
    const int bm0 = blockIdx.x * 128;
    const int bn0 = blockIdx.y * BN;

    const float* bm_ = bias + (size_t)sBm * m;

    // ---- pointer-increment fill state ----
    const int r0 = tid >> 3, u0 = tid & 7;
    const __half* aPtr = A + sAm * m + (size_t)(bm0 + r0) * KTOT + u0 * 8;
    const __half* bPtr = Wt + sWm * m + (size_t)(bn0 + r0) * KTOT + u0 * 8;
    const uint32_t dstA0 = sb + r0 * 128 + ((u0 ^ (r0 & 7)) << 4);  // swizzle p-invariant
    const uint32_t dstB0 = dstA0 + 128 * 128;

    auto fill = [&](int st) {
        uint32_t aD = dstA0 + st * STAGE_B;
#pragma unroll
        for (int p = 0; p < A_IT; p++)
            CPA(aD + p * (ROWS_P * 128),
                (const __half*)((const char*)aPtr + p * (ROWS_P * KTOT * 2)));
        uint32_t bD = dstB0 + st * STAGE_B;
#pragma unroll
        for (int p = 0; p < B_IT; p++)
            CPA(bD + p * (ROWS_P * 128),
                (const __half*)((const char*)bPtr + p * (ROWS_P * KTOT * 2)));
        CPA_COMMIT();
        aPtr += 64; bPtr += 64;       // advance one BK
    };

    float acc[MT][NT][4];
#pragma unroll
    for (int i = 0; i < MT; i++)
#pragma unroll
        for (int j = 0; j < NT; j++)
#pragma unroll
            for (int q = 0; q < 4; q++) acc[i][j][q] = 0.f;

    // per-lane ldmatrix bases and k-offsets (hoisted)
    const uint32_t aRow = sb + (wm * 64 + l15) * 128;
    const uint32_t bRow = sb + 128 * 128 + (wn * 32 + l15) * 128;
    uint32_t k4[4];
#pragma unroll
    for (int kk = 0; kk < 4; kk++)
        k4[kk] = (uint32_t)(((kk * 2 + hi) ^ xr) << 4);

    fill(0);
    fill(1);
    int stPre = 2 % 3;                 // next stage to fill

    for (int kb = 0; kb < NKB; kb++) {
        if (kb == NKB - 1) cpa_wait<0>(); else cpa_wait<1>();
        __syncthreads();
        if (kb + 2 < NKB) { fill(stPre); stPre = (stPre == 2) ? 0 : stPre + 1; }

        const uint32_t stOff = (uint32_t)((kb % 3) * STAGE_B);
#pragma unroll
        for (int kk = 0; kk < 4; kk++) {
            const uint32_t aK = aRow + stOff + k4[kk];
            const uint32_t bK = bRow + stOff + k4[kk];
            uint32_t afr[MT][4], bfr[NT][2];
#pragma unroll
            for (int mt = 0; mt < MT; mt++)
                ldm_x4(afr[mt], aK + mt * 2048);
#pragma unroll
            for (int ntp = 0; ntp < 2; ntp++) {       // B x4 covers 2 n-tiles
                uint32_t r[4];
                ldm_x4(r, bK + ntp * 2048);
                bfr[ntp * 2][0]     = r[0];
                bfr[ntp * 2 + 1][0] = r[1];
                bfr[ntp * 2][1]     = r[2];
                bfr[ntp * 2 + 1][1] = r[3];
            }
#pragma unroll
            for (int mt = 0; mt < MT; mt++)
#pragma unroll
                for (int nt = 0; nt < NT; nt++)
                    mma_f16(acc[mt][nt], afr[mt], bfr[nt]);
        }
    }

    // ---- epilogue ----
    // acc q: c0 (row gq, col 2tq) c1 (+1 col) c2 (+8 row) c3 (+8 row, +1 col)
    if (!HEADS) {
        __half* om = (__half*)outv + sOm * m;
#pragma unroll
        for (int nt = 0; nt < NT; nt++) {
            int gc0 = bn0 + wn * 32 + nt * 8 + tq * 2;
            float bA = bm_[gc0], bB = bm_[gc0 + 1];
#pragma unroll
            for (int mt = 0; mt < MT; mt++) {
                size_t gr = bm0 + wm * 64 + mt * 16 + gq;
                __half2 v0 = __floats2half2_rn(tanh_fast(acc[mt][nt][0] + bA),
                                               tanh_fast(acc[mt][nt][1] + bB));
                __half2 v1 = __floats2half2_rn(tanh_fast(acc[mt][nt][2] + bA),
                                               tanh_fast(acc[mt][nt][3] + bB));
                *(__half2*)(om + gr * ldO + gc0)       = v0;
                *(__half2*)(om + (gr + 8) * ldO + gc0) = v1;
            }
        }
    } else {
        float* out = (float*)outv;
#pragma unroll
        for (int nt = 0; nt < NT; nt++) {
#pragma unroll
            for (int q2 = 0; q2 < 2; q2++) {
                int gc = bn0 + wn * 32 + nt * 8 + tq * 2 + q2;
                if (gc >= 130) continue;
                float bb = bm_[gc];
#pragma unroll
                for (int mt = 0; mt < MT; mt++) {
#pragma unroll
                    for (int h = 0; h < 2; h++) {
                        int gr = bm0 + wm * 64 + mt * 16 + gq + h * 8;
                        float v = acc[mt][nt][h * 2 + q2] + bb;
                        if (gc < 64)
                            out[((size_t)m * BATCH + gr) * 64 + gc] = v;
                        else if (gc == 64)
                            out[OFF_MU_R + (size_t)m * BATCH + gr] = v;
                        else if (gc < 129)
                            out[OFF_LV_O + ((size_t)m * BATCH + gr) * 64 + (gc - 65)] = clampv(v);
                        else
                            out[OFF_LV_R + (size_t)m * BATCH + gr] = clampv(v);
                    }
                }
            }
        }
    }
}

// ---------------- Launch ----------------
extern "C" void kernel_launch(void* const* d_in, const int* in_sizes, int n_in,
                              void* d_out, int out_size) {
    const float* obs   = (const float*)d_in[0];
    const float* act   = (const float*)d_in[1];
    const float* W0    = (const float*)d_in[2];
    const float* b0    = (const float*)d_in[3];
    const float* W1    = (const float*)d_in[4];
    const float* b1    = (const float*)d_in[5];
    const float* W2    = (const float*)d_in[6];
    const float* b2    = (const float*)d_in[7];
    const float* Wmu_o = (const float*)d_in[8];
    const float* bmu_o = (const float*)d_in[9];
    const float* Wmu_r = (const float*)d_in[10];
    const float* bmu_r = (const float*)d_in[11];
    const float* Wv_o  = (const float*)d_in[12];
    const float* bv_o  = (const float*)d_in[13];
    const float* Wv_r  = (const float*)d_in[14];
    const float* bv_r  = (const float*)d_in[15];

    __half *px, *ph0, *ph1, *pwt0, *pwt1, *pwt2, *pwth;
    float *pbh;
    cudaGetSymbolAddress((void**)&px,   g_x);
    cudaGetSymbolAddress((void**)&ph0,  g_h0);
    cudaGetSymbolAddress((void**)&ph1,  g_h1);
    cudaGetSymbolAddress((void**)&pwt0, g_wt0);
    cudaGetSymbolAddress((void**)&pwt1, g_wt1);
    cudaGetSymbolAddress((void**)&pwt2, g_wt2);
    cudaGetSymbolAddress((void**)&pwth, g_wth);
    cudaGetSymbolAddress((void**)&pbh,  g_bh);

    // Layers: BM=128, BN=128, 8 warps of 64x32, 2 CTAs/SM (96KB smem).
    // Heads:  BM=128, BN=64, 4 warps, 3 CTAs/SM (72KB).
    const int SM_L = 3 * (128 + 128) * 128;      // 98304 B
    const int SM_H = 3 * (128 + 64) * 128;       // 73728 B
    cudaFuncSetAttribute((const void*)gemm_h<IN_PAD, 128, false>,
                         cudaFuncAttributeMaxDynamicSharedMemorySize, SM_L);
    cudaFuncSetAttribute((const void*)gemm_h<H_D, 128, false>,
                         cudaFuncAttributeMaxDynamicSharedMemorySize, SM_L);
    cudaFuncSetAttribute((const void*)gemm_h<H_D, 64, true>,
                         cudaFuncAttributeMaxDynamicSharedMemorySize, SM_H);

    // prep: 3 launches
    prep_fused<<<(M_ENS * HEAD_N * H_D + 255) / 256, 256>>>(
        obs, act, px, pwt0, Wmu_o, Wmu_r, Wv_o, Wv_r,
        bmu_o, bmu_r, bv_o, bv_r, pwth, pbh);
    transpose_h<false><<<dim3(IN_D / 32, H_D / 32, M_ENS), dim3(32, 8)>>>(
        W0, pwt0, nullptr, nullptr, IN_D, H_D, IN_PAD);
    transpose_h<true><<<dim3(H_D / 32, H_D / 32, 2 * M_ENS), dim3(32, 8)>>>(
        W1, pwt1, W2, pwt2, H_D, H_D, H_D);

    const size_t sH = (size_t)BATCH * H_D;
    dim3 gridL(BATCH / 128, H_D / 128, M_ENS);      // (32,8,8) = 2048 CTAs

    gemm_h<IN_PAD, 128, false><<<gridL, 256, SM_L>>>(
        px, 0, pwt0, (size_t)H_D * IN_PAD, b0, H_D, ph0, sH, H_D);
    gemm_h<H_D, 128, false><<<gridL, 256, SM_L>>>(
        ph0, sH, pwt1, (size_t)H_D * H_D, b1, H_D, ph1, sH, H_D);
    gemm_h<H_D, 128, false><<<gridL, 256, SM_L>>>(
        ph1, sH, pwt2, (size_t)H_D * H_D, b2, H_D, ph0, sH, H_D);

    dim3 gridH(BATCH / 128, HEAD_N / 64, M_ENS);    // (32,3,8)
    gemm_h<H_D, 64, true><<<gridH, 128, SM_H>>>(
        ph0, sH, pwth, (size_t)HEAD_N * H_D, pbh, HEAD_N, d_out, 0, 0);
}